// round 2
// baseline (speedup 1.0000x reference)
#include <cuda_runtime.h>
#include <math.h>

#define Nn 8192
#define IN_F 256
#define OUT_F 128
#define NWORDS 256   // bitmap words per row (8192 bits)
#define CAP 2048     // fast-path neighbor list capacity (expected degree ~32)

// ---------------- device scratch (no allocs allowed) ----------------
__device__ float    g_hc[Nn * OUT_F];          // 4 MB
__device__ unsigned g_adj[Nn * NWORDS];        // 8 MB adjacency bitmap
__device__ float    g_sc_src[Nn], g_sc_dst[Nn];
__device__ float    g_ss_src[Nn], g_ss_dst[Nn];
__device__ float    g_vs1[IN_F], g_vs2[IN_F];
__device__ float    g_scal[4];                 // ca, cs, bs1, bs2
__device__ int      g_isi32;

__device__ __forceinline__ float lrelu(float x) { return x > 0.f ? x : 0.01f * x; }

// ---------------- reductions (start and end with __syncthreads) ----------------
__device__ float blockReduceMax(float v, float* red) {
    __syncthreads();
    #pragma unroll
    for (int o = 16; o; o >>= 1) v = fmaxf(v, __shfl_xor_sync(0xffffffffu, v, o));
    int w = threadIdx.x >> 5;
    if ((threadIdx.x & 31) == 0) red[w] = v;
    __syncthreads();
    if (threadIdx.x < 32) {
        float x = (threadIdx.x < (blockDim.x >> 5)) ? red[threadIdx.x] : -INFINITY;
        #pragma unroll
        for (int o = 4; o; o >>= 1) x = fmaxf(x, __shfl_xor_sync(0xffffffffu, x, o));
        if (threadIdx.x == 0) red[0] = x;
    }
    __syncthreads();
    return red[0];
}

__device__ float blockReduceSum(float v, float* red) {
    __syncthreads();
    #pragma unroll
    for (int o = 16; o; o >>= 1) v += __shfl_xor_sync(0xffffffffu, v, o);
    int w = threadIdx.x >> 5;
    if ((threadIdx.x & 31) == 0) red[w] = v;
    __syncthreads();
    if (threadIdx.x < 32) {
        float x = (threadIdx.x < (blockDim.x >> 5)) ? red[threadIdx.x] : 0.f;
        #pragma unroll
        for (int o = 4; o; o >>= 1) x += __shfl_xor_sync(0xffffffffu, x, o);
        if (threadIdx.x == 0) red[0] = x;
    }
    __syncthreads();
    return red[0];
}

// ---------------- kernels ----------------
__global__ void k_clear() {
    int i = blockIdx.x * blockDim.x + threadIdx.x;
    if (i < Nn * NWORDS) g_adj[i] = 0u;
    if (i == 0) g_isi32 = 0;
}

// Detect whether edge_index is stored as int32 (JAX x64-disabled) or int64.
// If int64 little-endian with values < 8192, every odd int32 word is 0.
__global__ void k_detect(const int* __restrict__ p32, int E) {
    int t = blockIdx.x * blockDim.x + threadIdx.x;
    if (t < E) {
        if (p32[2 * t + 1] != 0) atomicOr(&g_isi32, 1);
    }
}

__global__ void k_edges(const int* __restrict__ p32, int E) {
    int e = blockIdx.x * blockDim.x + threadIdx.x;
    if (e >= E) return;
    int r, c;
    if (g_isi32) {
        r = p32[e];
        c = p32[E + e];
    } else {
        const long long* p64 = (const long long*)p32;
        r = (int)p64[e];
        c = (int)p64[E + e];
    }
    if ((unsigned)r < Nn && (unsigned)c < Nn)
        atomicOr(&g_adj[r * NWORDS + (c >> 5)], 1u << (c & 31));
}

// Fold hs-GEMM into two [256] vectors: vs = Ws_w^T @ as_half ; bias dots.
__global__ void k_pre(const float* __restrict__ Ws_w, const float* __restrict__ Ws_b,
                      const float* __restrict__ as_w,
                      const float* __restrict__ Ws_coff, const float* __restrict__ Wc_coff) {
    int k = threadIdx.x;  // 0..255
    float v1 = 0.f, v2 = 0.f;
    for (int f = 0; f < OUT_F; f++) {
        float w = Ws_w[f * IN_F + k];
        v1 += w * as_w[f];
        v2 += w * as_w[OUT_F + f];
    }
    g_vs1[k] = v1;
    g_vs2[k] = v2;
    if (k == 0) {
        float b1 = 0.f, b2 = 0.f;
        for (int f = 0; f < OUT_F; f++) {
            b1 += Ws_b[f] * as_w[f];
            b2 += Ws_b[f] * as_w[OUT_F + f];
        }
        g_scal[0] = fabsf(Ws_coff[0]);  // multiplies alpha_c (per reference)
        g_scal[1] = fabsf(Wc_coff[0]);  // multiplies alpha_s
        g_scal[2] = b1;
        g_scal[3] = b2;
    }
}

// Structure scores: per row, softmax over 256 features dotted with vs1/vs2.
__global__ void k_sscore(const float* __restrict__ hstruct) {
    int warp = (blockIdx.x * blockDim.x + threadIdx.x) >> 5;
    int lane = threadIdx.x & 31;
    if (warp >= Nn) return;
    const float* x = hstruct + (size_t)warp * IN_F;
    float v[8];
    float m = -INFINITY;
    #pragma unroll
    for (int e = 0; e < 8; e++) { v[e] = x[lane + 32 * e]; m = fmaxf(m, v[e]); }
    #pragma unroll
    for (int o = 16; o; o >>= 1) m = fmaxf(m, __shfl_xor_sync(0xffffffffu, m, o));
    float z = 0.f, d1 = 0.f, d2 = 0.f;
    #pragma unroll
    for (int e = 0; e < 8; e++) {
        float ex = __expf(v[e] - m);
        z  += ex;
        d1 += ex * g_vs1[lane + 32 * e];
        d2 += ex * g_vs2[lane + 32 * e];
    }
    #pragma unroll
    for (int o = 16; o; o >>= 1) {
        z  += __shfl_xor_sync(0xffffffffu, z,  o);
        d1 += __shfl_xor_sync(0xffffffffu, d1, o);
        d2 += __shfl_xor_sync(0xffffffffu, d2, o);
    }
    if (lane == 0) {
        g_ss_src[warp] = d1 / z + g_scal[2];
        g_ss_dst[warp] = d2 / z + g_scal[3];
    }
}

// hc = h_context @ Wc_w^T + Wc_b  (M=8192, N=128, K=256) fp32 tiled SGEMM.
#define BM 64
#define BN 128
#define BK 32
__global__ void __launch_bounds__(256) k_gemm(const float* __restrict__ A,
                                              const float* __restrict__ W,
                                              const float* __restrict__ b) {
    __shared__ float As[BK][BM + 4];
    __shared__ float Ws[BK][BN + 4];
    int tid = threadIdx.x;
    int block_m = blockIdx.x * BM;
    int tn = (tid & 31) * 4;   // 0..124
    int tm = (tid >> 5) * 8;   // 0..56
    float acc[8][4] = {};
    for (int k0 = 0; k0 < IN_F; k0 += BK) {
        #pragma unroll
        for (int i = 0; i < 2; i++) {
            int l = tid + i * 256;            // 0..511
            int row = l >> 3;
            int col4 = (l & 7) * 4;
            float4 v = *(const float4*)&A[(size_t)(block_m + row) * IN_F + k0 + col4];
            As[col4 + 0][row] = v.x; As[col4 + 1][row] = v.y;
            As[col4 + 2][row] = v.z; As[col4 + 3][row] = v.w;
        }
        #pragma unroll
        for (int i = 0; i < 4; i++) {
            int l = tid + i * 256;            // 0..1023
            int row = l >> 3;
            int col4 = (l & 7) * 4;
            float4 v = *(const float4*)&W[(size_t)row * IN_F + k0 + col4];
            Ws[col4 + 0][row] = v.x; Ws[col4 + 1][row] = v.y;
            Ws[col4 + 2][row] = v.z; Ws[col4 + 3][row] = v.w;
        }
        __syncthreads();
        #pragma unroll
        for (int k = 0; k < BK; k++) {
            float4 a0 = *(const float4*)&As[k][tm];
            float4 a1 = *(const float4*)&As[k][tm + 4];
            float4 w0 = *(const float4*)&Ws[k][tn];
            float af[8] = {a0.x, a0.y, a0.z, a0.w, a1.x, a1.y, a1.z, a1.w};
            float wf[4] = {w0.x, w0.y, w0.z, w0.w};
            #pragma unroll
            for (int i = 0; i < 8; i++)
                #pragma unroll
                for (int j = 0; j < 4; j++)
                    acc[i][j] += af[i] * wf[j];
        }
        __syncthreads();
    }
    #pragma unroll
    for (int i = 0; i < 8; i++) {
        int row = block_m + tm + i;
        #pragma unroll
        for (int j = 0; j < 4; j++)
            g_hc[(size_t)row * OUT_F + tn + j] = acc[i][j] + b[tn + j];
    }
}

// Context scores from hc (warp per row).
__global__ void k_cscore(const float* __restrict__ ac_w) {
    int warp = (blockIdx.x * blockDim.x + threadIdx.x) >> 5;
    int lane = threadIdx.x & 31;
    if (warp >= Nn) return;
    const float* h = g_hc + (size_t)warp * OUT_F;
    float s1 = 0.f, s2 = 0.f;
    #pragma unroll
    for (int e = 0; e < 4; e++) {
        int f = lane + 32 * e;
        float v = h[f];
        s1 += v * ac_w[f];
        s2 += v * ac_w[OUT_F + f];
    }
    #pragma unroll
    for (int o = 16; o; o >>= 1) {
        s1 += __shfl_xor_sync(0xffffffffu, s1, o);
        s2 += __shfl_xor_sync(0xffffffffu, s2, o);
    }
    if (lane == 0) { g_sc_src[warp] = s1; g_sc_dst[warp] = s2; }
}

// Per-row sparse masked softmax + weighted hc gather. STATIC smem only (~12.7 KB).
__global__ void __launch_bounds__(256) k_attn(float* __restrict__ out) {
    __shared__ float wl[CAP];
    __shared__ unsigned short jl[CAP];
    __shared__ float red[32];
    __shared__ int s_cnt;
    __shared__ float part2[OUT_F];

    int row = blockIdx.x;
    int tid = threadIdx.x;  // 256 threads, one bitmap word each
    float ca = g_scal[0], cs = g_scal[1];
    float sci = g_sc_src[row], ssi = g_ss_src[row];
    unsigned word = g_adj[row * NWORDS + tid];
    int f = tid & (OUT_F - 1);
    int part = tid >> 7;  // 0 or 1

    // total neighbor count
    if (tid == 0) s_cnt = 0;
    float totf = blockReduceSum((float)__popc(word), red);
    int total = (int)(totf + 0.5f);

    if (total == 0) {
        // masked row == all -9e15 -> uniform softmax -> mean of hc
        if (part == 0) {
            float acc = 0.f;
            for (int j = 0; j < Nn; j++) acc += g_hc[(size_t)j * OUT_F + f];
            out[(size_t)row * OUT_F + f] = acc / (float)Nn;
        }
        return;
    }

    // pass 1: max of alpha over set bits
    float m = -INFINITY;
    unsigned w = word;
    while (w) {
        int bpos = __ffs(w) - 1; w &= w - 1;
        int j = tid * 32 + bpos;
        float a = ca * lrelu(sci + g_sc_dst[j]) + cs * lrelu(ssi + g_ss_dst[j]);
        m = fmaxf(m, a);
    }
    m = blockReduceMax(m, red);   // internal syncs also make s_cnt=0 visible

    if (total <= CAP) {
        // fast path: single-shot compaction + gather
        int o = atomicAdd(&s_cnt, __popc(word));
        float zloc = 0.f;
        w = word;
        while (w) {
            int bpos = __ffs(w) - 1; w &= w - 1;
            int j = tid * 32 + bpos;
            float a = ca * lrelu(sci + g_sc_dst[j]) + cs * lrelu(ssi + g_ss_dst[j]);
            float e = __expf(a - m);
            zloc += e;
            wl[o] = e;
            jl[o] = (unsigned short)j;
            o++;
        }
        float Z = blockReduceSum(zloc, red);
        float inv = 1.f / Z;
        float acc = 0.f;
        for (int k = part; k < total; k += 2)
            acc += wl[k] * g_hc[(size_t)jl[k] * OUT_F + f];
        if (part == 1) part2[f] = acc;
        __syncthreads();
        if (part == 0)
            out[(size_t)row * OUT_F + f] = (acc + part2[f]) * inv;
        return;
    }

    // slow path (arbitrary degree): compute Z, then chunked compaction+gather
    {
        float zloc = 0.f;
        w = word;
        while (w) {
            int bpos = __ffs(w) - 1; w &= w - 1;
            int j = tid * 32 + bpos;
            float a = ca * lrelu(sci + g_sc_dst[j]) + cs * lrelu(ssi + g_ss_dst[j]);
            zloc += __expf(a - m);
        }
        float Z = blockReduceSum(zloc, red);
        float inv = 1.f / Z;
        float acc = 0.f;
        for (int c = 0; c < NWORDS / 32; c++) {   // 32 words = 1024 bits per chunk
            __syncthreads();
            if (tid == 0) s_cnt = 0;
            __syncthreads();
            if (tid < 32) {
                unsigned wd = g_adj[row * NWORDS + c * 32 + tid];
                int o = atomicAdd(&s_cnt, __popc(wd));
                while (wd) {
                    int bpos = __ffs(wd) - 1; wd &= wd - 1;
                    int j = (c * 32 + tid) * 32 + bpos;
                    float a = ca * lrelu(sci + g_sc_dst[j]) + cs * lrelu(ssi + g_ss_dst[j]);
                    wl[o] = __expf(a - m);
                    jl[o] = (unsigned short)j;
                    o++;
                }
            }
            __syncthreads();
            int cc = s_cnt;
            for (int k = part; k < cc; k += 2)
                acc += wl[k] * g_hc[(size_t)jl[k] * OUT_F + f];
        }
        if (part == 1) part2[f] = acc;
        __syncthreads();
        if (part == 0)
            out[(size_t)row * OUT_F + f] = (acc + part2[f]) * inv;
    }
}

// ---------------- launch ----------------
extern "C" void kernel_launch(void* const* d_in, const int* in_sizes, int n_in,
                              void* d_out, int out_size) {
    const float* h_context   = (const float*)d_in[0];
    const float* h_structure = (const float*)d_in[1];
    const int*   edge        = (const int*)d_in[2];   // int32 or int64, detected on device
    const float* Wc_w        = (const float*)d_in[3];
    const float* Wc_b        = (const float*)d_in[4];
    const float* Ws_w        = (const float*)d_in[5];
    const float* Ws_b        = (const float*)d_in[6];
    const float* ac_w        = (const float*)d_in[7];
    const float* as_w        = (const float*)d_in[8];
    const float* Ws_coff     = (const float*)d_in[9];
    const float* Wc_coff     = (const float*)d_in[10];
    float* out = (float*)d_out;
    int E = in_sizes[2] / 2;

    k_clear<<<(Nn * NWORDS + 255) / 256, 256>>>();
    k_detect<<<(E + 255) / 256, 256>>>(edge, E);
    k_edges<<<(E + 255) / 256, 256>>>(edge, E);
    k_pre<<<1, 256>>>(Ws_w, Ws_b, as_w, Ws_coff, Wc_coff);
    k_sscore<<<(Nn * 32 + 255) / 256, 256>>>(h_structure);
    k_gemm<<<Nn / BM, 256>>>(h_context, Wc_w, Wc_b);
    k_cscore<<<(Nn * 32 + 255) / 256, 256>>>(ac_w);
    k_attn<<<Nn, 256>>>(out);
}

// round 3
// speedup vs baseline: 1.1349x; 1.1349x over previous
#include <cuda_runtime.h>
#include <math.h>

#define Nn 8192
#define IN_F 256
#define OUT_F 128
#define NWORDS 256   // bitmap words per row (8192 bits)
#define CAP 2048     // fast-path neighbor list capacity (expected degree ~32)

// ---------------- device scratch (no allocs allowed) ----------------
__device__ float    g_hc[Nn * OUT_F];          // 4 MB
__device__ unsigned g_adj[Nn * NWORDS];        // 8 MB adjacency bitmap
__device__ float    g_sc_src[Nn], g_sc_dst[Nn];
__device__ float    g_ss_src[Nn], g_ss_dst[Nn];
__device__ float    g_vs1[IN_F], g_vs2[IN_F];
__device__ float    g_scal[4];                 // ca, cs, bs1, bs2
__device__ int      g_isi32;

__device__ __forceinline__ float lrelu(float x) { return x > 0.f ? x : 0.01f * x; }

// ---------------- reductions (start and end with __syncthreads) ----------------
__device__ float blockReduceMax(float v, float* red) {
    __syncthreads();
    #pragma unroll
    for (int o = 16; o; o >>= 1) v = fmaxf(v, __shfl_xor_sync(0xffffffffu, v, o));
    int w = threadIdx.x >> 5;
    if ((threadIdx.x & 31) == 0) red[w] = v;
    __syncthreads();
    if (threadIdx.x < 32) {
        float x = (threadIdx.x < (blockDim.x >> 5)) ? red[threadIdx.x] : -INFINITY;
        #pragma unroll
        for (int o = 4; o; o >>= 1) x = fmaxf(x, __shfl_xor_sync(0xffffffffu, x, o));
        if (threadIdx.x == 0) red[0] = x;
    }
    __syncthreads();
    return red[0];
}

__device__ float blockReduceSum(float v, float* red) {
    __syncthreads();
    #pragma unroll
    for (int o = 16; o; o >>= 1) v += __shfl_xor_sync(0xffffffffu, v, o);
    int w = threadIdx.x >> 5;
    if ((threadIdx.x & 31) == 0) red[w] = v;
    __syncthreads();
    if (threadIdx.x < 32) {
        float x = (threadIdx.x < (blockDim.x >> 5)) ? red[threadIdx.x] : 0.f;
        #pragma unroll
        for (int o = 4; o; o >>= 1) x += __shfl_xor_sync(0xffffffffu, x, o);
        if (threadIdx.x == 0) red[0] = x;
    }
    __syncthreads();
    return red[0];
}

// ---------------- kernels ----------------
// Vectorized bitmap clear (uint4) + flag reset.
__global__ void k_clear() {
    int i = blockIdx.x * blockDim.x + threadIdx.x;
    ((uint4*)g_adj)[i] = make_uint4(0u, 0u, 0u, 0u);
    if (i == 0) g_isi32 = 0;
}

// Detect whether edge_index is stored as int32 (JAX x64-disabled) or int64.
// If int64 little-endian with values < 8192, every odd int32 word is 0.
__global__ void k_detect(const int* __restrict__ p32, int E) {
    int t = blockIdx.x * blockDim.x + threadIdx.x;
    if (t < E) {
        if (p32[2 * t + 1] != 0) atomicOr(&g_isi32, 1);
    }
}

__global__ void k_edges(const int* __restrict__ p32, int E) {
    int e = blockIdx.x * blockDim.x + threadIdx.x;
    if (e >= E) return;
    int r, c;
    if (g_isi32) {
        r = p32[e];
        c = p32[E + e];
    } else {
        const long long* p64 = (const long long*)p32;
        r = (int)p64[e];
        c = (int)p64[E + e];
    }
    if ((unsigned)r < Nn && (unsigned)c < Nn)
        atomicOr(&g_adj[r * NWORDS + (c >> 5)], 1u << (c & 31));
}

// Fold hs-GEMM into two [256] vectors: vs = Ws_w^T @ as_half ; bias dots.
// 1024 threads: k = tid&255, 4-way partial split over f.
__global__ void __launch_bounds__(1024) k_pre(const float* __restrict__ Ws_w,
                                              const float* __restrict__ Ws_b,
                                              const float* __restrict__ as_w,
                                              const float* __restrict__ Ws_coff,
                                              const float* __restrict__ Wc_coff) {
    __shared__ float sp1[4][IN_F];
    __shared__ float sp2[4][IN_F];
    __shared__ float sb[2 * OUT_F];
    int tid = threadIdx.x;
    int k = tid & (IN_F - 1);
    int part = tid >> 8;  // 0..3
    float v1 = 0.f, v2 = 0.f;
    #pragma unroll
    for (int i = 0; i < 32; i++) {
        int f = part * 32 + i;
        float w = Ws_w[f * IN_F + k];
        v1 += w * as_w[f];
        v2 += w * as_w[OUT_F + f];
    }
    sp1[part][k] = v1;
    sp2[part][k] = v2;
    if (tid < OUT_F)            sb[tid] = Ws_b[tid] * as_w[tid];
    else if (tid < 2 * OUT_F)   sb[tid] = Ws_b[tid - OUT_F] * as_w[tid];
    __syncthreads();
    if (part == 0) {
        g_vs1[k] = sp1[0][k] + sp1[1][k] + sp1[2][k] + sp1[3][k];
        g_vs2[k] = sp2[0][k] + sp2[1][k] + sp2[2][k] + sp2[3][k];
    }
    if (tid == 0) {
        float b1 = 0.f, b2 = 0.f;
        #pragma unroll
        for (int f = 0; f < OUT_F; f++) { b1 += sb[f]; b2 += sb[OUT_F + f]; }
        g_scal[0] = fabsf(Ws_coff[0]);  // multiplies alpha_c
        g_scal[1] = fabsf(Wc_coff[0]);  // multiplies alpha_s
        g_scal[2] = b1;
        g_scal[3] = b2;
    }
}

// Structure scores: per row, softmax over 256 features dotted with vs1/vs2.
__global__ void k_sscore(const float* __restrict__ hstruct) {
    int warp = (blockIdx.x * blockDim.x + threadIdx.x) >> 5;
    int lane = threadIdx.x & 31;
    if (warp >= Nn) return;
    const float* x = hstruct + (size_t)warp * IN_F;
    float v[8];
    float m = -INFINITY;
    #pragma unroll
    for (int e = 0; e < 8; e++) { v[e] = x[lane + 32 * e]; m = fmaxf(m, v[e]); }
    #pragma unroll
    for (int o = 16; o; o >>= 1) m = fmaxf(m, __shfl_xor_sync(0xffffffffu, m, o));
    float z = 0.f, d1 = 0.f, d2 = 0.f;
    #pragma unroll
    for (int e = 0; e < 8; e++) {
        float ex = __expf(v[e] - m);
        z  += ex;
        d1 += ex * g_vs1[lane + 32 * e];
        d2 += ex * g_vs2[lane + 32 * e];
    }
    #pragma unroll
    for (int o = 16; o; o >>= 1) {
        z  += __shfl_xor_sync(0xffffffffu, z,  o);
        d1 += __shfl_xor_sync(0xffffffffu, d1, o);
        d2 += __shfl_xor_sync(0xffffffffu, d2, o);
    }
    if (lane == 0) {
        g_ss_src[warp] = d1 / z + g_scal[2];
        g_ss_dst[warp] = d2 / z + g_scal[3];
    }
}

// hc = h_context @ Wc_w^T + Wc_b  (M=8192, N=128, K=256) fp32 tiled SGEMM,
// with fused context-score epilogue (replaces k_cscore).
#define BM 64
#define BN 128
#define BK 32
__global__ void __launch_bounds__(256) k_gemm(const float* __restrict__ A,
                                              const float* __restrict__ W,
                                              const float* __restrict__ b,
                                              const float* __restrict__ ac_w) {
    __shared__ float As[BK][BM + 4];
    __shared__ float Ws[BK][BN + 4];
    int tid = threadIdx.x;
    int lane = tid & 31;
    int block_m = blockIdx.x * BM;
    int tn = lane * 4;         // 0..124
    int tm = (tid >> 5) * 8;   // 0..56
    float acc[8][4] = {};
    for (int k0 = 0; k0 < IN_F; k0 += BK) {
        #pragma unroll
        for (int i = 0; i < 2; i++) {
            int l = tid + i * 256;            // 0..511
            int row = l >> 3;
            int col4 = (l & 7) * 4;
            float4 v = *(const float4*)&A[(size_t)(block_m + row) * IN_F + k0 + col4];
            As[col4 + 0][row] = v.x; As[col4 + 1][row] = v.y;
            As[col4 + 2][row] = v.z; As[col4 + 3][row] = v.w;
        }
        #pragma unroll
        for (int i = 0; i < 4; i++) {
            int l = tid + i * 256;            // 0..1023
            int row = l >> 3;
            int col4 = (l & 7) * 4;
            float4 v = *(const float4*)&W[(size_t)row * IN_F + k0 + col4];
            Ws[col4 + 0][row] = v.x; Ws[col4 + 1][row] = v.y;
            Ws[col4 + 2][row] = v.z; Ws[col4 + 3][row] = v.w;
        }
        __syncthreads();
        #pragma unroll
        for (int k = 0; k < BK; k++) {
            float4 a0 = *(const float4*)&As[k][tm];
            float4 a1 = *(const float4*)&As[k][tm + 4];
            float4 w0 = *(const float4*)&Ws[k][tn];
            float af[8] = {a0.x, a0.y, a0.z, a0.w, a1.x, a1.y, a1.z, a1.w};
            float wf[4] = {w0.x, w0.y, w0.z, w0.w};
            #pragma unroll
            for (int i = 0; i < 8; i++)
                #pragma unroll
                for (int j = 0; j < 4; j++)
                    acc[i][j] += af[i] * wf[j];
        }
        __syncthreads();
    }
    float bb[4], ac1[4], ac2[4];
    #pragma unroll
    for (int j = 0; j < 4; j++) {
        bb[j]  = b[tn + j];
        ac1[j] = ac_w[tn + j];
        ac2[j] = ac_w[OUT_F + tn + j];
    }
    #pragma unroll
    for (int i = 0; i < 8; i++) {
        int row = block_m + tm + i;
        float s1 = 0.f, s2 = 0.f;
        float4 hv;
        float* hp = (float*)&hv;
        #pragma unroll
        for (int j = 0; j < 4; j++) {
            float h = acc[i][j] + bb[j];
            hp[j] = h;
            s1 += h * ac1[j];
            s2 += h * ac2[j];
        }
        *(float4*)&g_hc[(size_t)row * OUT_F + tn] = hv;
        // warp covers all 128 columns for this row -> full reduction
        #pragma unroll
        for (int o = 16; o; o >>= 1) {
            s1 += __shfl_xor_sync(0xffffffffu, s1, o);
            s2 += __shfl_xor_sync(0xffffffffu, s2, o);
        }
        if (lane == 0) { g_sc_src[row] = s1; g_sc_dst[row] = s2; }
    }
}

// Per-row sparse masked softmax + weighted hc gather. STATIC smem only (~12.7 KB).
__global__ void __launch_bounds__(256) k_attn(float* __restrict__ out) {
    __shared__ float wl[CAP];
    __shared__ unsigned short jl[CAP];
    __shared__ float red[32];
    __shared__ int s_cnt;
    __shared__ float part2[OUT_F];

    int row = blockIdx.x;
    int tid = threadIdx.x;  // 256 threads, one bitmap word each
    float ca = g_scal[0], cs = g_scal[1];
    float sci = g_sc_src[row], ssi = g_ss_src[row];
    unsigned word = g_adj[row * NWORDS + tid];
    int f = tid & (OUT_F - 1);
    int part = tid >> 7;  // 0 or 1

    // total neighbor count
    if (tid == 0) s_cnt = 0;
    float totf = blockReduceSum((float)__popc(word), red);
    int total = (int)(totf + 0.5f);

    if (total == 0) {
        // masked row == all -9e15 -> uniform softmax -> mean of hc
        if (part == 0) {
            float acc = 0.f;
            for (int j = 0; j < Nn; j++) acc += g_hc[(size_t)j * OUT_F + f];
            out[(size_t)row * OUT_F + f] = acc / (float)Nn;
        }
        return;
    }

    // pass 1: max of alpha over set bits
    float m = -INFINITY;
    unsigned w = word;
    while (w) {
        int bpos = __ffs(w) - 1; w &= w - 1;
        int j = tid * 32 + bpos;
        float a = ca * lrelu(sci + g_sc_dst[j]) + cs * lrelu(ssi + g_ss_dst[j]);
        m = fmaxf(m, a);
    }
    m = blockReduceMax(m, red);   // internal syncs also make s_cnt=0 visible

    if (total <= CAP) {
        // fast path: single-shot compaction + gather
        int o = atomicAdd(&s_cnt, __popc(word));
        float zloc = 0.f;
        w = word;
        while (w) {
            int bpos = __ffs(w) - 1; w &= w - 1;
            int j = tid * 32 + bpos;
            float a = ca * lrelu(sci + g_sc_dst[j]) + cs * lrelu(ssi + g_ss_dst[j]);
            float e = __expf(a - m);
            zloc += e;
            wl[o] = e;
            jl[o] = (unsigned short)j;
            o++;
        }
        float Z = blockReduceSum(zloc, red);
        float inv = 1.f / Z;
        float acc = 0.f;
        for (int k = part; k < total; k += 2)
            acc += wl[k] * g_hc[(size_t)jl[k] * OUT_F + f];
        if (part == 1) part2[f] = acc;
        __syncthreads();
        if (part == 0)
            out[(size_t)row * OUT_F + f] = (acc + part2[f]) * inv;
        return;
    }

    // slow path (arbitrary degree): compute Z, then chunked compaction+gather
    {
        float zloc = 0.f;
        w = word;
        while (w) {
            int bpos = __ffs(w) - 1; w &= w - 1;
            int j = tid * 32 + bpos;
            float a = ca * lrelu(sci + g_sc_dst[j]) + cs * lrelu(ssi + g_ss_dst[j]);
            zloc += __expf(a - m);
        }
        float Z = blockReduceSum(zloc, red);
        float inv = 1.f / Z;
        float acc = 0.f;
        for (int c = 0; c < NWORDS / 32; c++) {   // 32 words = 1024 bits per chunk
            __syncthreads();
            if (tid == 0) s_cnt = 0;
            __syncthreads();
            if (tid < 32) {
                unsigned wd = g_adj[row * NWORDS + c * 32 + tid];
                int o = atomicAdd(&s_cnt, __popc(wd));
                while (wd) {
                    int bpos = __ffs(wd) - 1; wd &= wd - 1;
                    int j = (c * 32 + tid) * 32 + bpos;
                    float a = ca * lrelu(sci + g_sc_dst[j]) + cs * lrelu(ssi + g_ss_dst[j]);
                    wl[o] = __expf(a - m);
                    jl[o] = (unsigned short)j;
                    o++;
                }
            }
            __syncthreads();
            int cc = s_cnt;
            for (int k = part; k < cc; k += 2)
                acc += wl[k] * g_hc[(size_t)jl[k] * OUT_F + f];
        }
        if (part == 1) part2[f] = acc;
        __syncthreads();
        if (part == 0)
            out[(size_t)row * OUT_F + f] = (acc + part2[f]) * inv;
    }
}

// ---------------- launch ----------------
extern "C" void kernel_launch(void* const* d_in, const int* in_sizes, int n_in,
                              void* d_out, int out_size) {
    const float* h_context   = (const float*)d_in[0];
    const float* h_structure = (const float*)d_in[1];
    const int*   edge        = (const int*)d_in[2];   // int32 or int64, detected on device
    const float* Wc_w        = (const float*)d_in[3];
    const float* Wc_b        = (const float*)d_in[4];
    const float* Ws_w        = (const float*)d_in[5];
    const float* Ws_b        = (const float*)d_in[6];
    const float* ac_w        = (const float*)d_in[7];
    const float* as_w        = (const float*)d_in[8];
    const float* Ws_coff     = (const float*)d_in[9];
    const float* Wc_coff     = (const float*)d_in[10];
    float* out = (float*)d_out;
    int E = in_sizes[2] / 2;

    k_clear<<<(Nn * NWORDS / 4) / 256, 256>>>();
    k_detect<<<(E + 255) / 256, 256>>>(edge, E);
    k_edges<<<(E + 255) / 256, 256>>>(edge, E);
    k_pre<<<1, 1024>>>(Ws_w, Ws_b, as_w, Ws_coff, Wc_coff);
    k_sscore<<<(Nn * 32 + 255) / 256, 256>>>(h_structure);
    k_gemm<<<Nn / BM, 256>>>(h_context, Wc_w, Wc_b, ac_w);
    k_attn<<<Nn, 256>>>(out);
}